// round 14
// baseline (speedup 1.0000x reference)
#include <cuda_runtime.h>

#define B_ 32
#define N_ 16384
#define D_ 256
#define S_ 8
#define CHUNKS 32
#define ROWS_PER_BLOCK (N_ / CHUNKS)   // 512
#define ROWS_PER_WARP  64
#define THREADS 256                    // 8 warps
#define EPSN 1e-12f
#define SEEDCAP 64
#define LISTCAP 1024

// ---- scratch (device globals: no allocations allowed) ----
__device__ float g_score[B_ * N_];     // stale-or-fresh score (UPPER BOUND on true)
__device__ float g_invsal[B_ * N_];    // 1/max(||row||, eps)  (exact, from pre)
__device__ int   g_last[B_ * N_];      // suppressions applied for slots j < g_last
__device__ float g_selhist[S_ * B_ * D_];  // exact fp32 selnorm history
__device__ float g_pval[B_ * CHUNKS];  // pre partial max (exact)
__device__ int   g_pidx[B_ * CHUNKS];  // pre partial argmax

__device__ __forceinline__ float warp_reduce_sum(float v) {
    #pragma unroll
    for (int o = 16; o; o >>= 1) v += __shfl_xor_sync(0xffffffffu, v, o);
    return v;
}

// -----------------------------------------------------------------------------
// Dummy: keeps ncu's fixed "-s 5 -c 1" window on lazy slot s=3 (launch 5).
// -----------------------------------------------------------------------------
__global__ void dummy_kernel() {}

// -----------------------------------------------------------------------------
// Pre: exact fp32 row norms -> score (=saliency) + invsal + last=0, and exact
// per-block argmax partials. Read-only streaming of f; NO fnorm materialized.
// grid = B*CHUNKS (=1024) x 256; warp per row, 64 rows/warp.
// -----------------------------------------------------------------------------
__global__ void __launch_bounds__(THREADS, 7) pre_kernel(const float* __restrict__ f) {
    int blk  = blockIdx.x;
    int b    = blk / CHUNKS;
    int c    = blk % CHUNKS;
    int warp = threadIdx.x >> 5;
    int lane = threadIdx.x & 31;
    int rbase = c * ROWS_PER_BLOCK;

    // init last-slot markers (coalesced)
    for (int i = threadIdx.x; i < ROWS_PER_BLOCK; i += THREADS)
        g_last[b * N_ + rbase + i] = 0;

    int row0 = rbase + warp * ROWS_PER_WARP;
    float bestV = -1.0f;
    int   bestI = 0x7fffffff;

    #pragma unroll 2
    for (int r = 0; r < ROWS_PER_WARP; ++r) {
        int row = row0 + r;
        const float4* p = (const float4*)(f + ((size_t)b * N_ + row) * D_);
        float4 a  = p[2 * lane];
        float4 bb = p[2 * lane + 1];
        float s = a.x*a.x + a.y*a.y + a.z*a.z + a.w*a.w
                + bb.x*bb.x + bb.y*bb.y + bb.z*bb.z + bb.w*bb.w;
        s = warp_reduce_sum(s);
        float nrm = sqrtf(s);
        if (lane == 0) {
            g_score[b * N_ + row]  = nrm;
            g_invsal[b * N_ + row] = 1.0f / fmaxf(nrm, EPSN);
        }
        if (nrm > bestV) { bestV = nrm; bestI = row; }   // ascending rows: > keeps low idx
    }

    __shared__ float sv[8];
    __shared__ int   si[8];
    if (lane == 0) { sv[warp] = bestV; si[warp] = bestI; }
    __syncthreads();
    if (threadIdx.x == 0) {
        float v = sv[0]; int i = si[0];
        #pragma unroll
        for (int w = 1; w < 8; ++w)
            if (sv[w] > v || (sv[w] == v && si[w] < i)) { v = sv[w]; i = si[w]; }
        g_pval[blk] = v;
        g_pidx[blk] = i;
    }
}

// -----------------------------------------------------------------------------
// Select slot 0: exact partial reduce; write out[0] + selhist[0] (= f*invsal).
// grid = B x 256.
// -----------------------------------------------------------------------------
__global__ void select0_kernel(const float* __restrict__ f, float* __restrict__ out) {
    int b = blockIdx.x;
    int t = threadIdx.x;
    __shared__ int s_win;

    if (t < 32) {
        float v = g_pval[b * CHUNKS + t];
        int   i = g_pidx[b * CHUNKS + t];
        #pragma unroll
        for (int o = 16; o; o >>= 1) {
            float ov = __shfl_xor_sync(0xffffffffu, v, o);
            int   oi = __shfl_xor_sync(0xffffffffu, i, o);
            if (ov > v || (ov == v && oi < i)) { v = ov; i = oi; }
        }
        if (t == 0) s_win = i;
    }
    __syncthreads();
    int w = s_win;
    float x = f[((size_t)b * N_ + w) * D_ + t];
    out[(size_t)b * S_ * D_ + t] = x;
    g_selhist[b * D_ + t] = x * g_invsal[b * N_ + w];
}

// -----------------------------------------------------------------------------
// Refresh one row (warp-collective): apply missing suppressions j in [last, s)
// in ascending order (exact fp32), store back, return new score (all lanes).
// -----------------------------------------------------------------------------
__device__ __forceinline__ float refresh_row(const float* __restrict__ f,
                                             int b, int r, int s,
                                             const float* hist, int lane) {
    const float4* p = (const float4*)(f + ((size_t)b * N_ + r) * D_);
    float4 a  = p[2 * lane];
    float4 c4 = p[2 * lane + 1];
    float invs  = g_invsal[b * N_ + r];
    float score = g_score[b * N_ + r];
    int   last  = g_last[b * N_ + r];
    for (int j = last; j < s; ++j) {
        const float4* h4 = (const float4*)&hist[j * D_ + lane * 8];
        float4 h0 = h4[0], h1 = h4[1];
        float d = a.x*h0.x + a.y*h0.y + a.z*h0.z + a.w*h0.w
                + c4.x*h1.x + c4.y*h1.y + c4.z*h1.z + c4.w*h1.w;
        d = warp_reduce_sum(d);
        float sim = d * invs;
        score *= (1.0f - fminf(fmaxf(sim, 0.0f), 1.0f));
    }
    if (lane == 0) { g_score[b * N_ + r] = score; g_last[b * N_ + r] = s; }
    return score;
}

// -----------------------------------------------------------------------------
// Lazy select for slot s (1..7): stale scores are upper bounds. Seed-refresh
// rows near the stale max, then certified wave loop: refresh ALL stale rows
// with bound >= exact champion until none remain. Exact argmax guaranteed
// regardless of capacities (waves loop on overflow). grid = B x 256.
// -----------------------------------------------------------------------------
__global__ void lazy_kernel(const float* __restrict__ f,
                            float* __restrict__ out, int s) {
    int b    = blockIdx.x;
    int t    = threadIdx.x;
    int warp = t >> 5;
    int lane = t & 31;

    __shared__ __align__(16) float hist[(S_ - 1) * D_];
    __shared__ int   list[LISTCAP];
    __shared__ int   s_cnt, s_ovf;
    __shared__ float s_vmax;
    __shared__ float s_champV;
    __shared__ int   s_champI;
    __shared__ float swv[8];
    __shared__ int   swi[8];

    // stage selnorm history (slots 0..s-1)
    for (int i = t; i < s * D_; i += THREADS) {
        int j = i >> 8, d = i & 255;
        hist[i] = g_selhist[(j * B_ + b) * D_ + d];
    }

    float* sc = g_score + b * N_;
    int*   la = g_last  + b * N_;

    // ---- stale argmax (all rows stale at kernel entry) ----
    float v = -1.0f; int vi = 0x7fffffff;
    for (int i = t; i < N_; i += THREADS) {
        float x = sc[i];
        if (x > v) { v = x; vi = i; }   // per-thread indices ascending
    }
    #pragma unroll
    for (int o = 16; o; o >>= 1) {
        float ov = __shfl_xor_sync(0xffffffffu, v, o);
        int   oi = __shfl_xor_sync(0xffffffffu, vi, o);
        if (ov > v || (ov == v && oi < vi)) { v = ov; vi = oi; }
    }
    if (lane == 0) { swv[warp] = v; swi[warp] = vi; }
    if (t == 0) { s_cnt = 0; s_ovf = 0; s_champV = -1.0f; s_champI = 0x7fffffff; }
    __syncthreads();
    if (t == 0) {
        float m = swv[0];
        #pragma unroll
        for (int w = 1; w < 8; ++w) m = fmaxf(m, swv[w]);
        s_vmax = m;
    }
    __syncthreads();

    // ---- seed: refresh rows with stale >= 0.98*vmax (heuristic; >=1 row) ----
    float thr = 0.98f * s_vmax;
    for (int i = t; i < N_; i += THREADS) {
        if (sc[i] >= thr) {
            int p = atomicAdd(&s_cnt, 1);
            if (p < SEEDCAP) list[p] = i;
        }
    }
    __syncthreads();
    {
        int cnt = min(s_cnt, SEEDCAP);
        float wv = -1.0f; int wi = 0x7fffffff;
        for (int ci = warp; ci < cnt; ci += 8) {
            int r = list[ci];
            float val = refresh_row(f, b, r, s, hist, lane);
            if (val > wv || (val == wv && r < wi)) { wv = val; wi = r; }
        }
        if (lane == 0) { swv[warp] = wv; swi[warp] = wi; }
        __syncthreads();
        if (t == 0) {
            float cv = -1.0f; int cix = 0x7fffffff;
            #pragma unroll
            for (int w = 0; w < 8; ++w)
                if (swv[w] > cv || (swv[w] == cv && swi[w] < cix)) { cv = swv[w]; cix = swi[w]; }
            s_champV = cv; s_champI = cix;
        }
        __syncthreads();
    }

    // ---- certified wave loop ----
    while (true) {
        if (t == 0) { s_cnt = 0; s_ovf = 0; }
        __syncthreads();
        float C = s_champV;
        for (int i = t; i < N_; i += THREADS) {
            if (la[i] < s && sc[i] >= C) {
                int p = atomicAdd(&s_cnt, 1);
                if (p < LISTCAP) list[p] = i; else s_ovf = 1;
            }
        }
        __syncthreads();
        int n   = min(s_cnt, LISTCAP);
        int ovf = s_ovf;
        if (n == 0) break;   // certified: no stale bound >= champion

        float wv = -1.0f; int wi = 0x7fffffff;
        for (int ci = warp; ci < n; ci += 8) {
            int r = list[ci];
            float val = refresh_row(f, b, r, s, hist, lane);
            if (val > wv || (val == wv && r < wi)) { wv = val; wi = r; }
        }
        if (lane == 0) { swv[warp] = wv; swi[warp] = wi; }
        __syncthreads();
        if (t == 0) {
            float cv = s_champV; int cix = s_champI;
            #pragma unroll
            for (int w = 0; w < 8; ++w)
                if (swv[w] > cv || (swv[w] == cv && swi[w] < cix)) { cv = swv[w]; cix = swi[w]; }
            s_champV = cv; s_champI = cix;
        }
        __syncthreads();
        if (!ovf) break;     // all qualifying rows refreshed; champion is exact argmax
    }

    // ---- write winner ----
    __syncthreads();
    int w = s_champI;
    float x = f[((size_t)b * N_ + w) * D_ + t];
    out[((size_t)b * S_ + s) * D_ + t] = x;
    g_selhist[((size_t)s * B_ + b) * D_ + t] = x * g_invsal[b * N_ + w];
}

// -----------------------------------------------------------------------------
extern "C" void kernel_launch(void* const* d_in, const int* in_sizes, int n_in,
                              void* d_out, int out_size) {
    const float* f = nullptr;
    long best = -1;
    for (int i = 0; i < n_in; ++i) {
        if ((long)in_sizes[i] > best) { best = in_sizes[i]; f = (const float*)d_in[i]; }
    }
    float* out = (float*)d_out;

    dummy_kernel<<<1, 32>>>();                 // ncu window -> lazy s=3 (launch 5)
    pre_kernel<<<B_ * CHUNKS, THREADS>>>(f);
    select0_kernel<<<B_, THREADS>>>(f, out);
    for (int s = 1; s < S_; ++s)
        lazy_kernel<<<B_, THREADS>>>(f, out, s);
}

// round 15
// speedup vs baseline: 1.0641x; 1.0641x over previous
#include <cuda_runtime.h>

#define B_ 32
#define N_ 16384
#define D_ 256
#define S_ 8
#define CHUNKS 32
#define ROWS_PER_BLOCK (N_ / CHUNKS)   // 512
#define ROWS_PER_WARP  64
#define THREADS 256                    // 8 warps
#define EPSN 1e-12f
#define SEEDCAP 64

// ---- scratch (device globals: no allocations allowed) ----
__device__ float g_score[B_ * N_];     // current bound (exact once refreshed to slot s)
__device__ float g_invsal[B_ * N_];    // 1/max(||row||, eps)  (exact, from pre)
__device__ int   g_last[B_ * N_];      // suppressions applied for slots j < g_last
__device__ float g_selhist[S_ * B_ * D_];           // exact fp32 selnorm history
__device__ float g_pval[B_ * CHUNKS];               // pre partial max (exact)
__device__ int   g_pidx[B_ * CHUNKS];               // pre partial argmax
__device__ unsigned long long g_champ[S_ * B_];     // packed (val_bits<<32)|~idx
__device__ float g_L[B_];                           // per-batch exact lower bound

__device__ __forceinline__ float warp_reduce_sum(float v) {
    #pragma unroll
    for (int o = 16; o; o >>= 1) v += __shfl_xor_sync(0xffffffffu, v, o);
    return v;
}

__device__ __forceinline__ unsigned long long pack_ch(float v, int idx) {
    // v >= 0 so float bits are order-preserving; ~idx makes lower idx win ties
    return ((unsigned long long)__float_as_uint(v) << 32)
         | (unsigned long long)(0xffffffffu - (unsigned)idx);
}
__device__ __forceinline__ int unpack_idx(unsigned long long p) {
    return (int)(0xffffffffu - (unsigned)(p & 0xffffffffull));
}

// -----------------------------------------------------------------------------
// Pre: exact fp32 row norms -> score(=saliency)+invsal+last=0, exact per-block
// argmax partials, zero champions. grid = B*CHUNKS x 256; warp/row, 64 rows.
// -----------------------------------------------------------------------------
__global__ void __launch_bounds__(THREADS, 7) pre_kernel(const float* __restrict__ f) {
    int blk  = blockIdx.x;
    int b    = blk / CHUNKS;
    int c    = blk % CHUNKS;
    int warp = threadIdx.x >> 5;
    int lane = threadIdx.x & 31;
    int rbase = c * ROWS_PER_BLOCK;

    if (blk == 0) g_champ[threadIdx.x] = 0ull;   // S_*B_ == 256 (graph-replay safe)
    for (int i = threadIdx.x; i < ROWS_PER_BLOCK; i += THREADS)
        g_last[b * N_ + rbase + i] = 0;

    int row0 = rbase + warp * ROWS_PER_WARP;
    float bestV = -1.0f;
    int   bestI = 0x7fffffff;

    #pragma unroll 2
    for (int r = 0; r < ROWS_PER_WARP; ++r) {
        int row = row0 + r;
        const float4* p = (const float4*)(f + ((size_t)b * N_ + row) * D_);
        float4 a  = p[2 * lane];
        float4 bb = p[2 * lane + 1];
        float s = a.x*a.x + a.y*a.y + a.z*a.z + a.w*a.w
                + bb.x*bb.x + bb.y*bb.y + bb.z*bb.z + bb.w*bb.w;
        s = warp_reduce_sum(s);
        float nrm = sqrtf(s);
        if (lane == 0) {
            g_score[b * N_ + row]  = nrm;
            g_invsal[b * N_ + row] = 1.0f / fmaxf(nrm, EPSN);
        }
        if (nrm > bestV) { bestV = nrm; bestI = row; }   // ascending rows: > keeps low idx
    }

    __shared__ float sv[8];
    __shared__ int   si[8];
    if (lane == 0) { sv[warp] = bestV; si[warp] = bestI; }
    __syncthreads();
    if (threadIdx.x == 0) {
        float v = sv[0]; int i = si[0];
        #pragma unroll
        for (int w = 1; w < 8; ++w)
            if (sv[w] > v || (sv[w] == v && si[w] < i)) { v = sv[w]; i = si[w]; }
        g_pval[blk] = v;
        g_pidx[blk] = i;
    }
}

// -----------------------------------------------------------------------------
// Select slot 0: exact partial reduce; write out[0] + selhist[0]. grid = B.
// -----------------------------------------------------------------------------
__global__ void select0_kernel(const float* __restrict__ f, float* __restrict__ out) {
    int b = blockIdx.x;
    int t = threadIdx.x;
    __shared__ int s_win;

    if (t < 32) {
        float v = g_pval[b * CHUNKS + t];
        int   i = g_pidx[b * CHUNKS + t];
        #pragma unroll
        for (int o = 16; o; o >>= 1) {
            float ov = __shfl_xor_sync(0xffffffffu, v, o);
            int   oi = __shfl_xor_sync(0xffffffffu, i, o);
            if (ov > v || (ov == v && oi < i)) { v = ov; i = oi; }
        }
        if (t == 0) s_win = i;
    }
    __syncthreads();
    int w = s_win;
    float x = f[((size_t)b * N_ + w) * D_ + t];
    out[(size_t)b * S_ * D_ + t] = x;
    g_selhist[b * D_ + t] = x * g_invsal[b * N_ + w];
}

// -----------------------------------------------------------------------------
// Refresh one row (warp-collective): apply missing suppressions [last, s)
// exactly in fp32 ascending order; store back; return new exact score.
// -----------------------------------------------------------------------------
__device__ __forceinline__ float refresh_row(const float* __restrict__ f,
                                             int b, int r, int s,
                                             const float* hist, int lane) {
    const float4* p = (const float4*)(f + ((size_t)b * N_ + r) * D_);
    float4 a  = p[2 * lane];
    float4 c4 = p[2 * lane + 1];
    float invs  = g_invsal[b * N_ + r];
    float score = g_score[b * N_ + r];
    int   last  = g_last[b * N_ + r];
    for (int j = last; j < s; ++j) {
        const float4* h4 = (const float4*)&hist[j * D_ + lane * 8];
        float4 h0 = h4[0], h1 = h4[1];
        float d = a.x*h0.x + a.y*h0.y + a.z*h0.z + a.w*h0.w
                + c4.x*h1.x + c4.y*h1.y + c4.z*h1.z + c4.w*h1.w;
        d = warp_reduce_sum(d);
        float sim = d * invs;
        score *= (1.0f - fminf(fmaxf(sim, 0.0f), 1.0f));
    }
    if (lane == 0) { g_score[b * N_ + r] = score; g_last[b * N_ + r] = s; }
    return score;
}

// -----------------------------------------------------------------------------
// Seed (grid=B): for s>=2 write winner(s-1) from champion; stage history; find
// stale max; refresh rows within 1% of it (cap 64) -> exact lower bound g_L[b]
// and initial champion for slot s.
// -----------------------------------------------------------------------------
__global__ void seed_kernel(const float* __restrict__ f,
                            float* __restrict__ out, int s) {
    int b    = blockIdx.x;
    int t    = threadIdx.x;
    int warp = t >> 5;
    int lane = t & 31;

    __shared__ __align__(16) float hist[(S_ - 1) * D_];
    __shared__ int   list[SEEDCAP];
    __shared__ int   s_cnt;
    __shared__ float swv[8];
    __shared__ float s_vmax;
    __shared__ unsigned long long s_champ;

    if (s >= 2) {   // write winner of slot s-1 (slot 0 handled by select0)
        unsigned long long pk = g_champ[(s - 1) * B_ + b];
        int w = unpack_idx(pk);
        float x = f[((size_t)b * N_ + w) * D_ + t];
        out[((size_t)b * S_ + (s - 1)) * D_ + t] = x;
        g_selhist[((size_t)(s - 1) * B_ + b) * D_ + t] = x * g_invsal[b * N_ + w];
        __syncthreads();
    }

    for (int i = t; i < s * D_; i += THREADS) {
        int j = i >> 8, d = i & 255;
        hist[i] = g_selhist[((size_t)j * B_ + b) * D_ + d];
    }
    if (t == 0) { s_cnt = 0; s_champ = 0ull; }

    const float* sc = g_score + b * N_;
    float v = -1.0f;
    for (int i = t; i < N_; i += THREADS) v = fmaxf(v, sc[i]);
    #pragma unroll
    for (int o = 16; o; o >>= 1) v = fmaxf(v, __shfl_xor_sync(0xffffffffu, v, o));
    if (lane == 0) swv[warp] = v;
    __syncthreads();
    if (t == 0) {
        float m = swv[0];
        #pragma unroll
        for (int w = 1; w < 8; ++w) m = fmaxf(m, swv[w]);
        s_vmax = m;
    }
    __syncthreads();

    float thr = 0.99f * s_vmax;
    for (int i = t; i < N_; i += THREADS) {
        if (sc[i] >= thr) {
            int p = atomicAdd(&s_cnt, 1);
            if (p < SEEDCAP) list[p] = i;
        }
    }
    __syncthreads();

    int n = min(s_cnt, SEEDCAP);   // >=1 (stale-max row always qualifies)
    for (int ci = warp; ci < n; ci += 8) {
        int r = list[ci];
        float val = refresh_row(f, b, r, s, hist, lane);
        if (lane == 0) atomicMax(&s_champ, pack_ch(val, r));
    }
    __syncthreads();
    if (t == 0) {
        atomicMax(&g_champ[s * B_ + b], s_champ);
        g_L[b] = __uint_as_float((unsigned)(s_champ >> 32));   // exact lower bound
    }
}

// -----------------------------------------------------------------------------
// Sweep (grid=B*CHUNKS): each block refreshes ALL rows in its 512-row chunk
// with last<s && bound >= L (certified exact set; <=512 so no overflow), folds
// exact values into the per-batch packed champion. grid = 1024 x 256.
// -----------------------------------------------------------------------------
__global__ void __launch_bounds__(THREADS, 7) sweep_kernel(const float* __restrict__ f, int s) {
    int blk  = blockIdx.x;
    int b    = blk / CHUNKS;
    int c    = blk % CHUNKS;
    int t    = threadIdx.x;
    int warp = t >> 5;
    int lane = t & 31;

    __shared__ __align__(16) float hist[(S_ - 1) * D_];
    __shared__ int   list[ROWS_PER_BLOCK];
    __shared__ int   s_cnt;
    __shared__ unsigned long long s_champ;

    for (int i = t; i < s * D_; i += THREADS) {
        int j = i >> 8, d = i & 255;
        hist[i] = g_selhist[((size_t)j * B_ + b) * D_ + d];
    }
    if (t == 0) { s_cnt = 0; s_champ = 0ull; }
    __syncthreads();

    float L = g_L[b];
    const float* sc = g_score + b * N_;
    const int*   la = g_last  + b * N_;
    int base = c * ROWS_PER_BLOCK;

    #pragma unroll 2
    for (int i = t; i < ROWS_PER_BLOCK; i += THREADS) {
        int r = base + i;
        if (la[r] < s && sc[r] >= L) {
            int p = atomicAdd(&s_cnt, 1);
            list[p] = r;                      // p < 512 guaranteed
        }
    }
    __syncthreads();

    int n = s_cnt;
    for (int ci = warp; ci < n; ci += 8) {
        int r = list[ci];
        float val = refresh_row(f, b, r, s, hist, lane);
        if (lane == 0) atomicMax(&s_champ, pack_ch(val, r));
    }
    __syncthreads();
    if (t == 0 && s_champ != 0ull)
        atomicMax(&g_champ[s * B_ + b], s_champ);
}

// -----------------------------------------------------------------------------
// Final: write winner of slot 7. grid = B x 256.
// -----------------------------------------------------------------------------
__global__ void final_kernel(const float* __restrict__ f, float* __restrict__ out) {
    int b = blockIdx.x;
    int t = threadIdx.x;
    int w = unpack_idx(g_champ[(S_ - 1) * B_ + b]);
    float x = f[((size_t)b * N_ + w) * D_ + t];
    out[((size_t)b * S_ + (S_ - 1)) * D_ + t] = x;
}

// -----------------------------------------------------------------------------
extern "C" void kernel_launch(void* const* d_in, const int* in_sizes, int n_in,
                              void* d_out, int out_size) {
    const float* f = nullptr;
    long best = -1;
    for (int i = 0; i < n_in; ++i) {
        if ((long)in_sizes[i] > best) { best = in_sizes[i]; f = (const float*)d_in[i]; }
    }
    float* out = (float*)d_out;

    pre_kernel<<<B_ * CHUNKS, THREADS>>>(f);       // launch 0
    select0_kernel<<<B_, THREADS>>>(f, out);       // launch 1
    for (int s = 1; s < S_; ++s) {
        seed_kernel<<<B_, THREADS>>>(f, out, s);   // 2,4,... (writes winner s-1 for s>=2)
        sweep_kernel<<<B_ * CHUNKS, THREADS>>>(f, s);  // 3,5 (ncu window: sweep s=2),...
    }
    final_kernel<<<B_, THREADS>>>(f, out);         // winner slot 7
}

// round 16
// speedup vs baseline: 2.2204x; 2.0867x over previous
#include <cuda_runtime.h>
#include <cuda_fp16.h>

#define B_ 32
#define N_ 16384
#define D_ 256
#define KB_ 32                         // k-blocks of 8 halves (D/8)
#define S_ 8
#define CHUNKS 32
#define ROWS_PER_BLOCK (N_ / CHUNKS)   // 512
#define THREADS 256                    // 8 warps
#define EPSN 1e-12f
#define BCAP 2048                      // per-batch candidate capacity (per slot)
#define MAXC 256                       // surviving-candidate capacity

// ---- scratch (device globals: no allocations allowed) ----
__device__ float  g_score[B_ * N_];                 // running score (approx after s>0)
__device__ __half g_fnorm[(size_t)B_ * KB_ * N_ * 8];  // transposed [b][kb][n][8] (256 MB)
__device__ float  g_selhist[(size_t)S_ * B_ * D_];  // exact fp32 selnorm history
__device__ float  g_salmax[B_];                     // exact max saliency per batch
__device__ float  g_pval[B_ * CHUNKS];              // per-block max (pre only, exact)
__device__ int    g_pidx[B_ * CHUNKS];              // per-block argmax idx (pre only)
// per-slot candidate lists: slot s entries written by update(s-1), read by update(s)/select(7)
__device__ int    g_bcnt2[S_ * B_];
__device__ int    g_gmax2[S_ * B_];                 // approx max (float bits, >=0)
__device__ int    g_bcand2[(size_t)S_ * B_ * BCAP];
__device__ float  g_bscore2[(size_t)S_ * B_ * BCAP];

__device__ __forceinline__ float block_reduce_sum(float v, float* red) {
    int lane = threadIdx.x & 31, warp = threadIdx.x >> 5;
    #pragma unroll
    for (int o = 16; o; o >>= 1) v += __shfl_xor_sync(0xffffffffu, v, o);
    if (lane == 0) red[warp] = v;
    __syncthreads();
    float tot = red[0] + red[1] + red[2] + red[3]
              + red[4] + red[5] + red[6] + red[7];
    __syncthreads();
    return tot;
}

__device__ __forceinline__ float block_reduce_max(float v, float* red) {
    int lane = threadIdx.x & 31, warp = threadIdx.x >> 5;
    #pragma unroll
    for (int o = 16; o; o >>= 1) v = fmaxf(v, __shfl_xor_sync(0xffffffffu, v, o));
    if (lane == 0) red[warp] = v;
    __syncthreads();
    float m = fmaxf(fmaxf(fmaxf(red[0], red[1]), fmaxf(red[2], red[3])),
                    fmaxf(fmaxf(red[4], red[5]), fmaxf(red[6], red[7])));
    __syncthreads();
    return m;
}

__device__ __forceinline__ float warp_reduce_sum(float v) {
    #pragma unroll
    for (int o = 16; o; o >>= 1) v += __shfl_xor_sync(0xffffffffu, v, o);
    return v;
}

// -----------------------------------------------------------------------------
// Pre: exact fp32 row norms -> score, fnorm fp16 TRANSPOSED via double-buffered
// 16-row staging tiles (occ 7 -> single wave). Streaming stores (__stcs).
// Zeroes per-slot candidate counters (graph-replay safe).
// -----------------------------------------------------------------------------
__device__ __forceinline__ void pre_compute_tile16(
    const float* __restrict__ f, int b, int trow0, int warp, int lane,
    float4 (*buf)[33], float& bestV, int& bestI)
{
    #pragma unroll
    for (int r = 0; r < 2; ++r) {
        int lrow = warp * 2 + r;
        int row  = trow0 + lrow;
        size_t base = ((size_t)b * N_ + row) * D_;
        const float4* p = (const float4*)(f + base);
        float4 a  = p[2 * lane];
        float4 bb = p[2 * lane + 1];
        float s = a.x*a.x + a.y*a.y + a.z*a.z + a.w*a.w
                + bb.x*bb.x + bb.y*bb.y + bb.z*bb.z + bb.w*bb.w;
        s = warp_reduce_sum(s);
        float nrm = sqrtf(s);
        float inv = 1.0f / fmaxf(nrm, EPSN);

        union { float4 v; __half2 h[4]; } u;
        u.h[0] = __floats2half2_rn(a.x * inv,  a.y * inv);
        u.h[1] = __floats2half2_rn(a.z * inv,  a.w * inv);
        u.h[2] = __floats2half2_rn(bb.x * inv, bb.y * inv);
        u.h[3] = __floats2half2_rn(bb.z * inv, bb.w * inv);
        buf[lrow][lane] = u.v;   // lane == kb

        if (lane == 0) g_score[b * N_ + row] = nrm;
        if (nrm > bestV) { bestV = nrm; bestI = row; }   // ascending rows: > keeps low idx
    }
}

__global__ void __launch_bounds__(THREADS, 7) pre_kernel(const float* __restrict__ f) {
    __shared__ float4 stage[2][16][33];   // 16.9 KB

    int blk  = blockIdx.x;
    int b    = blk / CHUNKS;
    int c    = blk % CHUNKS;
    int warp = threadIdx.x >> 5;
    int lane = threadIdx.x & 31;
    int rbase = c * ROWS_PER_BLOCK;
    const int NT = ROWS_PER_BLOCK / 16;   // 32 tiles

    // zero per-slot candidate state every run (graph replay safety)
    if (blk == 0) { g_bcnt2[threadIdx.x] = 0; g_gmax2[threadIdx.x] = 0; }  // S_*B_ == 256

    __half* fb = g_fnorm + (size_t)b * KB_ * N_ * 8;

    float bestV = -1.0f;
    int   bestI = 0x7fffffff;

    pre_compute_tile16(f, b, rbase, warp, lane, stage[0], bestV, bestI);

    for (int tile = 0; tile < NT; ++tile) {
        __syncthreads();
        int trow0 = rbase + tile * 16;
        float4 (*bufS)[33] = stage[tile & 1];
        // store: warp owns kb [4w,4w+4); 16 lanes per kb -> 256B contiguous runs
        #pragma unroll
        for (int q = 0; q < 2; ++q) {
            int kb  = warp * 4 + q * 2 + (lane >> 4);
            int row = lane & 15;
            float4 v = bufS[row][kb];
            __stcs((float4*)(fb + ((size_t)kb * N_ + trow0 + row) * 8), v);
        }
        if (tile + 1 < NT)
            pre_compute_tile16(f, b, rbase + (tile + 1) * 16, warp, lane,
                               stage[(tile + 1) & 1], bestV, bestI);
    }

    __shared__ float sv[8];
    __shared__ int   si[8];
    if (lane == 0) { sv[warp] = bestV; si[warp] = bestI; }
    __syncthreads();
    if (threadIdx.x == 0) {
        float v = sv[0]; int i = si[0];
        #pragma unroll
        for (int w = 1; w < 8; ++w)
            if (sv[w] > v || (sv[w] == v && si[w] < i)) { v = sv[w]; i = si[w]; }
        g_pval[blk] = v;
        g_pidx[blk] = i;
    }
}

// -----------------------------------------------------------------------------
// Update (suppression for slot s) with FUSED winner derivation:
//   s==0: derive winner from exact pre partials (select0 fused away).
//   s>=1: derive from per-slot candidate list (identical data+code per block).
// Block c==0 writes out[s] + g_selhist[s] (+ g_salmax for s==0).
// Streaming loop unchanged (proven 73.9% DRAM) except __ldcs on fnorm.
// Appends slot-(s+1) candidates. grid = B*CHUNKS (=1024) x 256.
// -----------------------------------------------------------------------------
__global__ void __launch_bounds__(THREADS, 7) update_kernel(
    const float* __restrict__ f, float* __restrict__ out, int s)
{
    int blk  = blockIdx.x;
    int b    = blk / CHUNKS;
    int c    = blk % CHUNKS;
    int t    = threadIdx.x;
    int warp = t >> 5;
    int lane = t & 31;

    __shared__ __align__(16) float ssel[D_];
    __shared__ __align__(16) float hist[S_ * D_];
    __shared__ float red[8];
    __shared__ float s_thr;
    __shared__ int   s_cnt, s_ovf, s_win;
    __shared__ int   list[MAXC];
    __shared__ float swv[8];
    __shared__ int   swi[8];

    float salmax_loc;

    if (s == 0) {
        // ---- fused select0: exact argmax of saliency from pre partials ----
        if (t < 32) {
            float v = g_pval[b * CHUNKS + t];
            int   i = g_pidx[b * CHUNKS + t];
            #pragma unroll
            for (int o = 16; o; o >>= 1) {
                float ov = __shfl_xor_sync(0xffffffffu, v, o);
                int   oi = __shfl_xor_sync(0xffffffffu, i, o);
                if (ov > v || (ov == v && oi < i)) { v = ov; i = oi; }
            }
            if (t == 0) s_win = i;
        }
        __syncthreads();
        int w = s_win;
        float x = f[((size_t)b * N_ + w) * D_ + t];
        float sal2 = block_reduce_sum(x * x, red);
        float sal  = sqrtf(sal2);
        float inv  = 1.0f / fmaxf(sal, EPSN);
        float sn   = x * inv;
        ssel[t] = sn;
        salmax_loc = sal;                 // winner's norm == exact max saliency
        if (c == 0) {
            out[(size_t)b * S_ * D_ + t] = x;
            g_selhist[b * D_ + t] = sn;
            if (t == 0) g_salmax[b] = sal;
        }
        __syncthreads();
    } else {
        // ---- derive winner(s) from candidate list (slot s) ----
        if (t == 0) { s_cnt = 0; s_ovf = 0; }
        __syncthreads();
        salmax_loc = g_salmax[b];
        int   cnt  = g_bcnt2[s * B_ + b];
        float gmax = __int_as_float(g_gmax2[s * B_ + b]);
        int   m    = min(cnt, BCAP);
        if (cnt > BCAP && t == 0) s_ovf = 1;
        __syncthreads();

        float margin = salmax_loc * (float)s * 3e-3f;
        float thr;
        const size_t lbase = ((size_t)s * B_ + b) * BCAP;

        if (s_ovf) {   // rigorous fallback (practically unreachable)
            float lv = -1.0f;
            for (int i = t; i < N_; i += THREADS)
                lv = fmaxf(lv, g_score[b * N_ + i]);
            gmax = block_reduce_max(lv, red);
            thr = gmax - margin;
            for (int i = t; i < N_; i += THREADS) {
                if (g_score[b * N_ + i] >= thr) {
                    int p = atomicAdd(&s_cnt, 1);
                    if (p < MAXC) list[p] = i;
                }
            }
            __syncthreads();
        } else {
            thr = gmax - margin;
            for (int i = t; i < m; i += THREADS) {
                if (g_bscore2[lbase + i] >= thr) {
                    int p = atomicAdd(&s_cnt, 1);
                    if (p < MAXC) list[p] = g_bcand2[lbase + i];
                }
            }
            __syncthreads();
        }

        int nc = min(s_cnt, MAXC);
        int winner;
        if (nc == 1) {
            winner = list[0];
        } else {
            // stage selnorm history, then warp-parallel exact fp32 rescore
            for (int i = t; i < s * D_; i += THREADS) {
                int j = i >> 8, d = i & 255;
                hist[i] = g_selhist[((size_t)j * B_ + b) * D_ + d];
            }
            __syncthreads();
            float wv = -1.0f; int wi = 0x7fffffff;
            for (int ci = warp; ci < nc; ci += 8) {
                int idx = list[ci];
                const float4* p = (const float4*)(f + ((size_t)b * N_ + idx) * D_);
                float4 a  = p[2 * lane];
                float4 bb = p[2 * lane + 1];
                float ss = a.x*a.x + a.y*a.y + a.z*a.z + a.w*a.w
                         + bb.x*bb.x + bb.y*bb.y + bb.z*bb.z + bb.w*bb.w;
                ss = warp_reduce_sum(ss);
                float sal = sqrtf(ss);
                float inv = 1.0f / fmaxf(sal, EPSN);
                float supp = 1.0f;
                for (int j = 0; j < s; ++j) {
                    const float4* h4 = (const float4*)&hist[j * D_ + lane * 8];
                    float4 h0 = h4[0], h1 = h4[1];
                    float d = a.x*h0.x + a.y*h0.y + a.z*h0.z + a.w*h0.w
                            + bb.x*h1.x + bb.y*h1.y + bb.z*h1.z + bb.w*h1.w;
                    d = warp_reduce_sum(d) * inv;
                    supp *= (1.0f - fminf(fmaxf(d, 0.0f), 1.0f));
                }
                float scv = sal * supp;
                if (scv > wv || (scv == wv && idx < wi)) { wv = scv; wi = idx; }
            }
            if (lane == 0) { swv[warp] = wv; swi[warp] = wi; }
            __syncthreads();
            if (t == 0) {
                float v = swv[0]; int i = swi[0];
                #pragma unroll
                for (int w = 1; w < 8; ++w)
                    if (swv[w] > v || (swv[w] == v && swi[w] < i)) { v = swv[w]; i = swi[w]; }
                s_win = i;
            }
            __syncthreads();
            winner = s_win;
        }

        float x = f[((size_t)b * N_ + winner) * D_ + t];
        float sal2 = block_reduce_sum(x * x, red);
        float inv  = 1.0f / fmaxf(sqrtf(sal2), EPSN);
        float sn   = x * inv;
        ssel[t] = sn;
        if (c == 0) {
            out[((size_t)b * S_ + s) * D_ + t] = x;
            g_selhist[((size_t)s * B_ + b) * D_ + t] = sn;
        }
        __syncthreads();
    }

    // ---- streaming suppression (proven loop; __ldcs on fnorm) ----
    int n0 = c * ROWS_PER_BLOCK + t;            // rows n0 and n0+256
    const __half* fb = g_fnorm + (size_t)b * KB_ * N_ * 8;

    float acc0 = 0.0f, acc1 = 0.0f;
    #pragma unroll 2
    for (int kb = 0; kb < KB_; ++kb) {
        float4 se0 = *(const float4*)&ssel[kb * 8];
        float4 se1 = *(const float4*)&ssel[kb * 8 + 4];
        const __half* kbase = fb + (size_t)kb * N_ * 8;
        float4 r0 = __ldcs((const float4*)(kbase + (size_t)n0 * 8));
        float4 r1 = __ldcs((const float4*)(kbase + (size_t)(n0 + 256) * 8));

        __half2* h0 = (__half2*)&r0;
        __half2* h1 = (__half2*)&r1;
        float2 a;
        a = __half22float2(h0[0]); acc0 = fmaf(a.x, se0.x, acc0); acc0 = fmaf(a.y, se0.y, acc0);
        a = __half22float2(h0[1]); acc0 = fmaf(a.x, se0.z, acc0); acc0 = fmaf(a.y, se0.w, acc0);
        a = __half22float2(h0[2]); acc0 = fmaf(a.x, se1.x, acc0); acc0 = fmaf(a.y, se1.y, acc0);
        a = __half22float2(h0[3]); acc0 = fmaf(a.x, se1.z, acc0); acc0 = fmaf(a.y, se1.w, acc0);
        a = __half22float2(h1[0]); acc1 = fmaf(a.x, se0.x, acc1); acc1 = fmaf(a.y, se0.y, acc1);
        a = __half22float2(h1[1]); acc1 = fmaf(a.x, se0.z, acc1); acc1 = fmaf(a.y, se0.w, acc1);
        a = __half22float2(h1[2]); acc1 = fmaf(a.x, se1.x, acc1); acc1 = fmaf(a.y, se1.y, acc1);
        a = __half22float2(h1[3]); acc1 = fmaf(a.x, se1.z, acc1); acc1 = fmaf(a.y, se1.w, acc1);
    }

    float sc0 = g_score[b * N_ + n0];
    float sc1 = g_score[b * N_ + n0 + 256];
    float ns0 = sc0 * (1.0f - fminf(fmaxf(acc0, 0.0f), 1.0f));
    float ns1 = sc1 * (1.0f - fminf(fmaxf(acc1, 0.0f), 1.0f));
    g_score[b * N_ + n0]       = ns0;
    g_score[b * N_ + n0 + 256] = ns1;

    float bmax = block_reduce_max(fmaxf(ns0, ns1), red);
    if (t == 0)
        s_thr = bmax - salmax_loc * (float)(s + 1) * 3e-3f;  // superset of global-margin set
    __syncthreads();
    float thr2 = s_thr;

    int*   cnt_p  = &g_bcnt2[(s + 1) * B_ + b];
    int*   gmax_p = &g_gmax2[(s + 1) * B_ + b];
    size_t abase  = ((size_t)(s + 1) * B_ + b) * BCAP;
    if (ns0 >= thr2) {
        int p = atomicAdd(cnt_p, 1);
        atomicMax(gmax_p, __float_as_int(ns0));   // scores >= 0: int order == float order
        if (p < BCAP) { g_bcand2[abase + p] = n0;       g_bscore2[abase + p] = ns0; }
    }
    if (ns1 >= thr2) {
        int p = atomicAdd(cnt_p, 1);
        atomicMax(gmax_p, __float_as_int(ns1));
        if (p < BCAP) { g_bcand2[abase + p] = n0 + 256; g_bscore2[abase + p] = ns1; }
    }
}

// -----------------------------------------------------------------------------
// Final select (slot 7 only): winner from candidate list, exact verification
// when >1 survives. grid = B x 256.
// -----------------------------------------------------------------------------
__global__ void select_kernel(const float* __restrict__ f,
                              float* __restrict__ out, int slot) {
    int b    = blockIdx.x;
    int t    = threadIdx.x;
    int warp = t >> 5;
    int lane = t & 31;

    __shared__ float red[8];
    __shared__ __align__(16) float hist[S_ * D_];
    __shared__ int   s_cnt, s_ovf, s_win;
    __shared__ int   list[MAXC];
    __shared__ float swv[8];
    __shared__ int   swi[8];

    if (t == 0) { s_cnt = 0; s_ovf = 0; }
    __syncthreads();

    int   cnt  = g_bcnt2[slot * B_ + b];
    float gmax = __int_as_float(g_gmax2[slot * B_ + b]);
    int   m    = min(cnt, BCAP);
    if (cnt > BCAP && t == 0) s_ovf = 1;
    __syncthreads();

    float margin = g_salmax[b] * (float)slot * 3e-3f;
    float thr;
    const size_t lbase = ((size_t)slot * B_ + b) * BCAP;

    if (s_ovf) {
        float lv = -1.0f;
        for (int i = t; i < N_; i += THREADS)
            lv = fmaxf(lv, g_score[b * N_ + i]);
        gmax = block_reduce_max(lv, red);
        thr = gmax - margin;
        for (int i = t; i < N_; i += THREADS) {
            if (g_score[b * N_ + i] >= thr) {
                int p = atomicAdd(&s_cnt, 1);
                if (p < MAXC) list[p] = i;
            }
        }
        __syncthreads();
    } else {
        thr = gmax - margin;
        for (int i = t; i < m; i += THREADS) {
            if (g_bscore2[lbase + i] >= thr) {
                int p = atomicAdd(&s_cnt, 1);
                if (p < MAXC) list[p] = g_bcand2[lbase + i];
            }
        }
        __syncthreads();
    }

    int nc = min(s_cnt, MAXC);
    int winner;
    if (nc == 1) {
        winner = list[0];
    } else {
        for (int i = t; i < slot * D_; i += THREADS) {
            int j = i >> 8, d = i & 255;
            hist[i] = g_selhist[((size_t)j * B_ + b) * D_ + d];
        }
        __syncthreads();
        float wv = -1.0f; int wi = 0x7fffffff;
        for (int ci = warp; ci < nc; ci += 8) {
            int idx = list[ci];
            const float4* p = (const float4*)(f + ((size_t)b * N_ + idx) * D_);
            float4 a  = p[2 * lane];
            float4 bb = p[2 * lane + 1];
            float ss = a.x*a.x + a.y*a.y + a.z*a.z + a.w*a.w
                     + bb.x*bb.x + bb.y*bb.y + bb.z*bb.z + bb.w*bb.w;
            ss = warp_reduce_sum(ss);
            float sal = sqrtf(ss);
            float inv = 1.0f / fmaxf(sal, EPSN);
            float supp = 1.0f;
            for (int j = 0; j < slot; ++j) {
                const float4* h4 = (const float4*)&hist[j * D_ + lane * 8];
                float4 h0 = h4[0], h1 = h4[1];
                float d = a.x*h0.x + a.y*h0.y + a.z*h0.z + a.w*h0.w
                        + bb.x*h1.x + bb.y*h1.y + bb.z*h1.z + bb.w*h1.w;
                d = warp_reduce_sum(d) * inv;
                supp *= (1.0f - fminf(fmaxf(d, 0.0f), 1.0f));
            }
            float scv = sal * supp;
            if (scv > wv || (scv == wv && idx < wi)) { wv = scv; wi = idx; }
        }
        if (lane == 0) { swv[warp] = wv; swi[warp] = wi; }
        __syncthreads();
        if (t == 0) {
            float v = swv[0]; int i = swi[0];
            #pragma unroll
            for (int w = 1; w < 8; ++w)
                if (swv[w] > v || (swv[w] == v && swi[w] < i)) { v = swv[w]; i = swi[w]; }
            s_win = i;
        }
        __syncthreads();
        winner = s_win;
    }

    float x = f[((size_t)b * N_ + winner) * D_ + t];
    out[((size_t)b * S_ + slot) * D_ + t] = x;
}

// -----------------------------------------------------------------------------
extern "C" void kernel_launch(void* const* d_in, const int* in_sizes, int n_in,
                              void* d_out, int out_size) {
    const float* f = nullptr;
    long best = -1;
    for (int i = 0; i < n_in; ++i) {
        if ((long)in_sizes[i] > best) { best = in_sizes[i]; f = (const float*)d_in[i]; }
    }
    float* out = (float*)d_out;

    pre_kernel<<<B_ * CHUNKS, THREADS>>>(f);                  // launch 0
    for (int s = 0; s < S_ - 1; ++s)
        update_kernel<<<B_ * CHUNKS, THREADS>>>(f, out, s);   // 1..7 (ncu -s5: upd s=4)
    select_kernel<<<B_, THREADS>>>(f, out, S_ - 1);           // final slot 7
}

// round 17
// speedup vs baseline: 2.2523x; 1.0144x over previous
#include <cuda_runtime.h>
#include <cuda_fp16.h>

#define B_ 32
#define N_ 16384
#define D_ 256
#define KB_ 32                         // k-blocks of 8 halves (D/8)
#define S_ 8
#define CHUNKS 32
#define ROWS_PER_BLOCK (N_ / CHUNKS)   // 512
#define THREADS 256                    // 8 warps
#define EPSN 1e-12f
#define BCAP 2048                      // per-batch candidate capacity (per slot)
#define MAXC 256                       // surviving-candidate capacity
// fp16 sim error <= 2^-11 per pass (rigorous 4.9e-4); two-sided 2eps = 9.8e-4/slot.
// 1.5e-3 keeps >50% headroom while shrinking candidate sets ~2.5x vs 3e-3.
#define MARGIN_EPS 1.5e-3f

// ---- scratch (device globals: no allocations allowed) ----
__device__ float  g_score[B_ * N_];                 // running score (approx after s>0)
__device__ __half g_fnorm[(size_t)B_ * KB_ * N_ * 8];  // transposed [b][kb][n][8] (256 MB)
__device__ float  g_selhist[(size_t)S_ * B_ * D_];  // exact fp32 selnorm history
__device__ float  g_salmax[B_];                     // exact max saliency per batch
__device__ float  g_pval[B_ * CHUNKS];              // per-block max (pre only, exact)
__device__ int    g_pidx[B_ * CHUNKS];              // per-block argmax idx (pre only)
// per-slot candidate lists: slot s entries written by update(s-1), read by update(s)/select(7)
__device__ int    g_bcnt2[S_ * B_];
__device__ int    g_gmax2[S_ * B_];                 // approx max (float bits, >=0)
__device__ int    g_bcand2[(size_t)S_ * B_ * BCAP];
__device__ float  g_bscore2[(size_t)S_ * B_ * BCAP];

__device__ __forceinline__ float block_reduce_sum(float v, float* red) {
    int lane = threadIdx.x & 31, warp = threadIdx.x >> 5;
    #pragma unroll
    for (int o = 16; o; o >>= 1) v += __shfl_xor_sync(0xffffffffu, v, o);
    if (lane == 0) red[warp] = v;
    __syncthreads();
    float tot = red[0] + red[1] + red[2] + red[3]
              + red[4] + red[5] + red[6] + red[7];
    __syncthreads();
    return tot;
}

__device__ __forceinline__ float block_reduce_max(float v, float* red) {
    int lane = threadIdx.x & 31, warp = threadIdx.x >> 5;
    #pragma unroll
    for (int o = 16; o; o >>= 1) v = fmaxf(v, __shfl_xor_sync(0xffffffffu, v, o));
    if (lane == 0) red[warp] = v;
    __syncthreads();
    float m = fmaxf(fmaxf(fmaxf(red[0], red[1]), fmaxf(red[2], red[3])),
                    fmaxf(fmaxf(red[4], red[5]), fmaxf(red[6], red[7])));
    __syncthreads();
    return m;
}

__device__ __forceinline__ float warp_reduce_sum(float v) {
    #pragma unroll
    for (int o = 16; o; o >>= 1) v += __shfl_xor_sync(0xffffffffu, v, o);
    return v;
}

// -----------------------------------------------------------------------------
// Pre: exact fp32 row norms -> score, fnorm fp16 TRANSPOSED via double-buffered
// 16-row staging tiles (occ 7 -> single wave). Streaming stores (__stcs).
// Zeroes per-slot candidate counters (graph-replay safe).
// -----------------------------------------------------------------------------
__device__ __forceinline__ void pre_compute_tile16(
    const float* __restrict__ f, int b, int trow0, int warp, int lane,
    float4 (*buf)[33], float& bestV, int& bestI)
{
    #pragma unroll
    for (int r = 0; r < 2; ++r) {
        int lrow = warp * 2 + r;
        int row  = trow0 + lrow;
        size_t base = ((size_t)b * N_ + row) * D_;
        const float4* p = (const float4*)(f + base);
        float4 a  = p[2 * lane];
        float4 bb = p[2 * lane + 1];
        float s = a.x*a.x + a.y*a.y + a.z*a.z + a.w*a.w
                + bb.x*bb.x + bb.y*bb.y + bb.z*bb.z + bb.w*bb.w;
        s = warp_reduce_sum(s);
        float nrm = sqrtf(s);
        float inv = 1.0f / fmaxf(nrm, EPSN);

        union { float4 v; __half2 h[4]; } u;
        u.h[0] = __floats2half2_rn(a.x * inv,  a.y * inv);
        u.h[1] = __floats2half2_rn(a.z * inv,  a.w * inv);
        u.h[2] = __floats2half2_rn(bb.x * inv, bb.y * inv);
        u.h[3] = __floats2half2_rn(bb.z * inv, bb.w * inv);
        buf[lrow][lane] = u.v;   // lane == kb

        if (lane == 0) g_score[b * N_ + row] = nrm;
        if (nrm > bestV) { bestV = nrm; bestI = row; }   // ascending rows: > keeps low idx
    }
}

__global__ void __launch_bounds__(THREADS, 7) pre_kernel(const float* __restrict__ f) {
    __shared__ float4 stage[2][16][33];   // 16.9 KB

    int blk  = blockIdx.x;
    int b    = blk / CHUNKS;
    int c    = blk % CHUNKS;
    int warp = threadIdx.x >> 5;
    int lane = threadIdx.x & 31;
    int rbase = c * ROWS_PER_BLOCK;
    const int NT = ROWS_PER_BLOCK / 16;   // 32 tiles

    // zero per-slot candidate state every run (graph replay safety)
    if (blk == 0) { g_bcnt2[threadIdx.x] = 0; g_gmax2[threadIdx.x] = 0; }  // S_*B_ == 256

    __half* fb = g_fnorm + (size_t)b * KB_ * N_ * 8;

    float bestV = -1.0f;
    int   bestI = 0x7fffffff;

    pre_compute_tile16(f, b, rbase, warp, lane, stage[0], bestV, bestI);

    for (int tile = 0; tile < NT; ++tile) {
        __syncthreads();
        int trow0 = rbase + tile * 16;
        float4 (*bufS)[33] = stage[tile & 1];
        // store: warp owns kb [4w,4w+4); 16 lanes per kb -> 256B contiguous runs
        #pragma unroll
        for (int q = 0; q < 2; ++q) {
            int kb  = warp * 4 + q * 2 + (lane >> 4);
            int row = lane & 15;
            float4 v = bufS[row][kb];
            __stcs((float4*)(fb + ((size_t)kb * N_ + trow0 + row) * 8), v);
        }
        if (tile + 1 < NT)
            pre_compute_tile16(f, b, rbase + (tile + 1) * 16, warp, lane,
                               stage[(tile + 1) & 1], bestV, bestI);
    }

    __shared__ float sv[8];
    __shared__ int   si[8];
    if (lane == 0) { sv[warp] = bestV; si[warp] = bestI; }
    __syncthreads();
    if (threadIdx.x == 0) {
        float v = sv[0]; int i = si[0];
        #pragma unroll
        for (int w = 1; w < 8; ++w)
            if (sv[w] > v || (sv[w] == v && si[w] < i)) { v = sv[w]; i = si[w]; }
        g_pval[blk] = v;
        g_pidx[blk] = i;
    }
}

// -----------------------------------------------------------------------------
// Update (suppression for slot s) with FUSED winner derivation:
//   s==0: derive winner from exact pre partials.
//   s>=1: derive from per-slot candidate list (identical data+code per block;
//         nc==1 fast path is the common case with the tightened margin).
// Block c==0 writes out[s] + g_selhist[s] (+ g_salmax for s==0).
// Streaming loop proven (73.9% DRAM); score loads hoisted above kb loop.
// Appends slot-(s+1) candidates. grid = B*CHUNKS (=1024) x 256.
// -----------------------------------------------------------------------------
__global__ void __launch_bounds__(THREADS, 7) update_kernel(
    const float* __restrict__ f, float* __restrict__ out, int s)
{
    int blk  = blockIdx.x;
    int b    = blk / CHUNKS;
    int c    = blk % CHUNKS;
    int t    = threadIdx.x;
    int warp = t >> 5;
    int lane = t & 31;

    __shared__ __align__(16) float ssel[D_];
    __shared__ __align__(16) float hist[S_ * D_];
    __shared__ float red[8];
    __shared__ float s_thr;
    __shared__ int   s_cnt, s_ovf, s_win;
    __shared__ int   list[MAXC];
    __shared__ float swv[8];
    __shared__ int   swi[8];

    float salmax_loc;

    if (s == 0) {
        // ---- fused select0: exact argmax of saliency from pre partials ----
        if (t < 32) {
            float v = g_pval[b * CHUNKS + t];
            int   i = g_pidx[b * CHUNKS + t];
            #pragma unroll
            for (int o = 16; o; o >>= 1) {
                float ov = __shfl_xor_sync(0xffffffffu, v, o);
                int   oi = __shfl_xor_sync(0xffffffffu, i, o);
                if (ov > v || (ov == v && oi < i)) { v = ov; i = oi; }
            }
            if (t == 0) s_win = i;
        }
        __syncthreads();
        int w = s_win;
        float x = f[((size_t)b * N_ + w) * D_ + t];
        float sal2 = block_reduce_sum(x * x, red);
        float sal  = sqrtf(sal2);
        float inv  = 1.0f / fmaxf(sal, EPSN);
        float sn   = x * inv;
        ssel[t] = sn;
        salmax_loc = sal;                 // winner's norm == exact max saliency
        if (c == 0) {
            out[(size_t)b * S_ * D_ + t] = x;
            g_selhist[b * D_ + t] = sn;
            if (t == 0) g_salmax[b] = sal;
        }
        __syncthreads();
    } else {
        // ---- derive winner(s) from candidate list (slot s) ----
        if (t == 0) { s_cnt = 0; s_ovf = 0; }
        __syncthreads();
        salmax_loc = g_salmax[b];
        int   cnt  = g_bcnt2[s * B_ + b];
        float gmax = __int_as_float(g_gmax2[s * B_ + b]);
        int   m    = min(cnt, BCAP);
        if (cnt > BCAP && t == 0) s_ovf = 1;
        __syncthreads();

        float margin = salmax_loc * (float)s * MARGIN_EPS;
        float thr;
        const size_t lbase = ((size_t)s * B_ + b) * BCAP;

        if (s_ovf) {   // rigorous fallback (practically unreachable)
            float lv = -1.0f;
            for (int i = t; i < N_; i += THREADS)
                lv = fmaxf(lv, g_score[b * N_ + i]);
            gmax = block_reduce_max(lv, red);
            thr = gmax - margin;
            for (int i = t; i < N_; i += THREADS) {
                if (g_score[b * N_ + i] >= thr) {
                    int p = atomicAdd(&s_cnt, 1);
                    if (p < MAXC) list[p] = i;
                }
            }
            __syncthreads();
        } else {
            thr = gmax - margin;
            for (int i = t; i < m; i += THREADS) {
                if (g_bscore2[lbase + i] >= thr) {
                    int p = atomicAdd(&s_cnt, 1);
                    if (p < MAXC) list[p] = g_bcand2[lbase + i];
                }
            }
            __syncthreads();
        }

        int nc = min(s_cnt, MAXC);
        int winner;
        if (nc == 1) {
            winner = list[0];
        } else {
            // stage selnorm history, then warp-parallel exact fp32 rescore
            for (int i = t; i < s * D_; i += THREADS) {
                int j = i >> 8, d = i & 255;
                hist[i] = g_selhist[((size_t)j * B_ + b) * D_ + d];
            }
            __syncthreads();
            float wv = -1.0f; int wi = 0x7fffffff;
            for (int ci = warp; ci < nc; ci += 8) {
                int idx = list[ci];
                const float4* p = (const float4*)(f + ((size_t)b * N_ + idx) * D_);
                float4 a  = p[2 * lane];
                float4 bb = p[2 * lane + 1];
                float ss = a.x*a.x + a.y*a.y + a.z*a.z + a.w*a.w
                         + bb.x*bb.x + bb.y*bb.y + bb.z*bb.z + bb.w*bb.w;
                ss = warp_reduce_sum(ss);
                float sal = sqrtf(ss);
                float inv = 1.0f / fmaxf(sal, EPSN);
                float supp = 1.0f;
                for (int j = 0; j < s; ++j) {
                    const float4* h4 = (const float4*)&hist[j * D_ + lane * 8];
                    float4 h0 = h4[0], h1 = h4[1];
                    float d = a.x*h0.x + a.y*h0.y + a.z*h0.z + a.w*h0.w
                            + bb.x*h1.x + bb.y*h1.y + bb.z*h1.z + bb.w*h1.w;
                    d = warp_reduce_sum(d) * inv;
                    supp *= (1.0f - fminf(fmaxf(d, 0.0f), 1.0f));
                }
                float scv = sal * supp;
                if (scv > wv || (scv == wv && idx < wi)) { wv = scv; wi = idx; }
            }
            if (lane == 0) { swv[warp] = wv; swi[warp] = wi; }
            __syncthreads();
            if (t == 0) {
                float v = swv[0]; int i = swi[0];
                #pragma unroll
                for (int w = 1; w < 8; ++w)
                    if (swv[w] > v || (swv[w] == v && swi[w] < i)) { v = swv[w]; i = swi[w]; }
                s_win = i;
            }
            __syncthreads();
            winner = s_win;
        }

        float x = f[((size_t)b * N_ + winner) * D_ + t];
        float sal2 = block_reduce_sum(x * x, red);
        float inv  = 1.0f / fmaxf(sqrtf(sal2), EPSN);
        float sn   = x * inv;
        ssel[t] = sn;
        if (c == 0) {
            out[((size_t)b * S_ + s) * D_ + t] = x;
            g_selhist[((size_t)s * B_ + b) * D_ + t] = sn;
        }
        __syncthreads();
    }

    // ---- streaming suppression (proven loop; score loads hoisted) ----
    int n0 = c * ROWS_PER_BLOCK + t;            // rows n0 and n0+256
    const __half* fb = g_fnorm + (size_t)b * KB_ * N_ * 8;

    float sc0 = g_score[b * N_ + n0];           // hoisted: overlap with kb loop
    float sc1 = g_score[b * N_ + n0 + 256];

    float acc0 = 0.0f, acc1 = 0.0f;
    #pragma unroll 2
    for (int kb = 0; kb < KB_; ++kb) {
        float4 se0 = *(const float4*)&ssel[kb * 8];
        float4 se1 = *(const float4*)&ssel[kb * 8 + 4];
        const __half* kbase = fb + (size_t)kb * N_ * 8;
        float4 r0 = __ldcs((const float4*)(kbase + (size_t)n0 * 8));
        float4 r1 = __ldcs((const float4*)(kbase + (size_t)(n0 + 256) * 8));

        __half2* h0 = (__half2*)&r0;
        __half2* h1 = (__half2*)&r1;
        float2 a;
        a = __half22float2(h0[0]); acc0 = fmaf(a.x, se0.x, acc0); acc0 = fmaf(a.y, se0.y, acc0);
        a = __half22float2(h0[1]); acc0 = fmaf(a.x, se0.z, acc0); acc0 = fmaf(a.y, se0.w, acc0);
        a = __half22float2(h0[2]); acc0 = fmaf(a.x, se1.x, acc0); acc0 = fmaf(a.y, se1.y, acc0);
        a = __half22float2(h0[3]); acc0 = fmaf(a.x, se1.z, acc0); acc0 = fmaf(a.y, se1.w, acc0);
        a = __half22float2(h1[0]); acc1 = fmaf(a.x, se0.x, acc1); acc1 = fmaf(a.y, se0.y, acc1);
        a = __half22float2(h1[1]); acc1 = fmaf(a.x, se0.z, acc1); acc1 = fmaf(a.y, se0.w, acc1);
        a = __half22float2(h1[2]); acc1 = fmaf(a.x, se1.x, acc1); acc1 = fmaf(a.y, se1.y, acc1);
        a = __half22float2(h1[3]); acc1 = fmaf(a.x, se1.z, acc1); acc1 = fmaf(a.y, se1.w, acc1);
    }

    float ns0 = sc0 * (1.0f - fminf(fmaxf(acc0, 0.0f), 1.0f));
    float ns1 = sc1 * (1.0f - fminf(fmaxf(acc1, 0.0f), 1.0f));
    g_score[b * N_ + n0]       = ns0;
    g_score[b * N_ + n0 + 256] = ns1;

    float bmax = block_reduce_max(fmaxf(ns0, ns1), red);
    if (t == 0)
        s_thr = bmax - salmax_loc * (float)(s + 1) * MARGIN_EPS;  // superset of global set
    __syncthreads();
    float thr2 = s_thr;

    int*   cnt_p  = &g_bcnt2[(s + 1) * B_ + b];
    int*   gmax_p = &g_gmax2[(s + 1) * B_ + b];
    size_t abase  = ((size_t)(s + 1) * B_ + b) * BCAP;
    if (ns0 >= thr2) {
        int p = atomicAdd(cnt_p, 1);
        atomicMax(gmax_p, __float_as_int(ns0));   // scores >= 0: int order == float order
        if (p < BCAP) { g_bcand2[abase + p] = n0;       g_bscore2[abase + p] = ns0; }
    }
    if (ns1 >= thr2) {
        int p = atomicAdd(cnt_p, 1);
        atomicMax(gmax_p, __float_as_int(ns1));
        if (p < BCAP) { g_bcand2[abase + p] = n0 + 256; g_bscore2[abase + p] = ns1; }
    }
}

// -----------------------------------------------------------------------------
// Final select (slot 7 only): winner from candidate list, exact verification
// when >1 survives. grid = B x 256.
// -----------------------------------------------------------------------------
__global__ void select_kernel(const float* __restrict__ f,
                              float* __restrict__ out, int slot) {
    int b    = blockIdx.x;
    int t    = threadIdx.x;
    int warp = t >> 5;
    int lane = t & 31;

    __shared__ float red[8];
    __shared__ __align__(16) float hist[S_ * D_];
    __shared__ int   s_cnt, s_ovf, s_win;
    __shared__ int   list[MAXC];
    __shared__ float swv[8];
    __shared__ int   swi[8];

    if (t == 0) { s_cnt = 0; s_ovf = 0; }
    __syncthreads();

    int   cnt  = g_bcnt2[slot * B_ + b];
    float gmax = __int_as_float(g_gmax2[slot * B_ + b]);
    int   m    = min(cnt, BCAP);
    if (cnt > BCAP && t == 0) s_ovf = 1;
    __syncthreads();

    float margin = g_salmax[b] * (float)slot * MARGIN_EPS;
    float thr;
    const size_t lbase = ((size_t)slot * B_ + b) * BCAP;

    if (s_ovf) {
        float lv = -1.0f;
        for (int i = t; i < N_; i += THREADS)
            lv = fmaxf(lv, g_score[b * N_ + i]);
        gmax = block_reduce_max(lv, red);
        thr = gmax - margin;
        for (int i = t; i < N_; i += THREADS) {
            if (g_score[b * N_ + i] >= thr) {
                int p = atomicAdd(&s_cnt, 1);
                if (p < MAXC) list[p] = i;
            }
        }
        __syncthreads();
    } else {
        thr = gmax - margin;
        for (int i = t; i < m; i += THREADS) {
            if (g_bscore2[lbase + i] >= thr) {
                int p = atomicAdd(&s_cnt, 1);
                if (p < MAXC) list[p] = g_bcand2[lbase + i];
            }
        }
        __syncthreads();
    }

    int nc = min(s_cnt, MAXC);
    int winner;
    if (nc == 1) {
        winner = list[0];
    } else {
        for (int i = t; i < slot * D_; i += THREADS) {
            int j = i >> 8, d = i & 255;
            hist[i] = g_selhist[((size_t)j * B_ + b) * D_ + d];
        }
        __syncthreads();
        float wv = -1.0f; int wi = 0x7fffffff;
        for (int ci = warp; ci < nc; ci += 8) {
            int idx = list[ci];
            const float4* p = (const float4*)(f + ((size_t)b * N_ + idx) * D_);
            float4 a  = p[2 * lane];
            float4 bb = p[2 * lane + 1];
            float ss = a.x*a.x + a.y*a.y + a.z*a.z + a.w*a.w
                     + bb.x*bb.x + bb.y*bb.y + bb.z*bb.z + bb.w*bb.w;
            ss = warp_reduce_sum(ss);
            float sal = sqrtf(ss);
            float inv = 1.0f / fmaxf(sal, EPSN);
            float supp = 1.0f;
            for (int j = 0; j < slot; ++j) {
                const float4* h4 = (const float4*)&hist[j * D_ + lane * 8];
                float4 h0 = h4[0], h1 = h4[1];
                float d = a.x*h0.x + a.y*h0.y + a.z*h0.z + a.w*h0.w
                        + bb.x*h1.x + bb.y*h1.y + bb.z*h1.z + bb.w*h1.w;
                d = warp_reduce_sum(d) * inv;
                supp *= (1.0f - fminf(fmaxf(d, 0.0f), 1.0f));
            }
            float scv = sal * supp;
            if (scv > wv || (scv == wv && idx < wi)) { wv = scv; wi = idx; }
        }
        if (lane == 0) { swv[warp] = wv; swi[warp] = wi; }
        __syncthreads();
        if (t == 0) {
            float v = swv[0]; int i = swi[0];
            #pragma unroll
            for (int w = 1; w < 8; ++w)
                if (swv[w] > v || (swv[w] == v && swi[w] < i)) { v = swv[w]; i = swi[w]; }
            s_win = i;
        }
        __syncthreads();
        winner = s_win;
    }

    float x = f[((size_t)b * N_ + winner) * D_ + t];
    out[((size_t)b * S_ + slot) * D_ + t] = x;
}

// -----------------------------------------------------------------------------
extern "C" void kernel_launch(void* const* d_in, const int* in_sizes, int n_in,
                              void* d_out, int out_size) {
    const float* f = nullptr;
    long best = -1;
    for (int i = 0; i < n_in; ++i) {
        if ((long)in_sizes[i] > best) { best = in_sizes[i]; f = (const float*)d_in[i]; }
    }
    float* out = (float*)d_out;

    pre_kernel<<<B_ * CHUNKS, THREADS>>>(f);                  // launch 0
    for (int s = 0; s < S_ - 1; ++s)
        update_kernel<<<B_ * CHUNKS, THREADS>>>(f, out, s);   // 1..7 (ncu -s5: upd s=4)
    select_kernel<<<B_, THREADS>>>(f, out, S_ - 1);           // final slot 7
}